// round 1
// baseline (speedup 1.0000x reference)
#include <cuda_runtime.h>
#include <math.h>

#define ALPHA 1.3f
#define GNEPS 1e-5f
// B=64, M=1024, D=1024, H=8, HD=128

// ---------------- scratch (__device__ globals; no allocation allowed) --------
__device__ float g_qbuf[64 * 1024];            // projected q   (b,h,c) = b*1024+h*128+c
__device__ float g_v1buf[64 * 1024];           // projected v1
__device__ float g_dotb[64 * 8 * 1024];        // q . k  per (b,h,m)
__device__ float g_knb[64 * 8 * 1024];         // ||k||  per (b,h,m)
__device__ float g_v2s[67108864];              // v2 projected, layout ((b*8+h)*1024+m)*128+c

__device__ __forceinline__ float celu_f(float x) {
    return x > 0.f ? x : ALPHA * expm1f(x * (1.0f / ALPHA));
}

// ---------------- small projections: q, v1 (64 rows) ------------------------
// grid = 64*8 blocks, 128 threads. block = (row, head). Fused CELU + GroupNorm.
template <int DST>  // 0 -> g_qbuf, 1 -> g_v1buf
__global__ __launch_bounds__(128) void small_proj_kernel(
    const float* __restrict__ X, const float* __restrict__ W,
    const float* __restrict__ bias, const float* __restrict__ gw,
    const float* __restrict__ betaw)
{
    __shared__ float xs[1024];
    __shared__ float rs[4], rs2[4];
    const int row = blockIdx.x >> 3;
    const int h   = blockIdx.x & 7;
    const int c   = threadIdx.x;

    const float4* xr = (const float4*)(X + (size_t)row * 1024);
    float4* xs4 = (float4*)xs;
    for (int i = c; i < 256; i += 128) xs4[i] = xr[i];
    __syncthreads();

    const int col = h * 128 + c;
    float acc = bias[col];
    const float* Wp = W + col;
#pragma unroll 8
    for (int k = 0; k < 1024; k++) acc = fmaf(xs[k], Wp[(size_t)k * 1024], acc);
    acc = celu_f(acc);

    float s = acc, s2 = acc * acc;
#pragma unroll
    for (int o = 16; o; o >>= 1) {
        s  += __shfl_xor_sync(0xffffffffu, s,  o);
        s2 += __shfl_xor_sync(0xffffffffu, s2, o);
    }
    if ((c & 31) == 0) { rs[c >> 5] = s; rs2[c >> 5] = s2; }
    __syncthreads();
    s  = rs[0] + rs[1] + rs[2] + rs[3];
    s2 = rs2[0] + rs2[1] + rs2[2] + rs2[3];
    const float mu   = s * (1.f / 128.f);
    const float rstd = rsqrtf(s2 * (1.f / 128.f) - mu * mu + GNEPS);
    const float v = (acc - mu) * rstd * gw[col] + betaw[col];
    if (DST == 0) g_qbuf[row * 1024 + col] = v;
    else          g_v1buf[row * 1024 + col] = v;
}

// ---------------- big projection GEMM: 65536x1024 @ 1024x1024 ----------------
// BM=BN=128, BK=16, 256 threads, 8x8/thread. N-tile == one head == one GN group,
// and each 128-row tile stays inside one batch element (1024 % 128 == 0).
// MODE 0 (k): epilogue reduces straight to dot[b,h,m], kn[b,h,m]; k never stored.
// MODE 1 (v2): epilogue stores normalized v2 into g_v2s in (b,h,m,c) layout.
template <int MODE>
__global__ __launch_bounds__(256, 2) void big_proj_kernel(
    const float* __restrict__ A, const float* __restrict__ W,
    const float* __restrict__ bias, const float* __restrict__ gw,
    const float* __restrict__ betaw)
{
    __shared__ float As[16][132];   // transposed A tile, padded stride (keeps LDS.128 aligned)
    __shared__ float Bs[16][128];
    __shared__ float colp[4][128];  // bias, g, beta, q(head slice)

    const int h    = blockIdx.x;        // 0..7
    const int row0 = blockIdx.y * 128;  // 0..65408
    const int col0 = h * 128;
    const int b    = row0 >> 10;
    const int tid  = threadIdx.x;
    const int tx   = tid & 15, ty = tid >> 4;

    if (tid < 128) {
        colp[0][tid] = bias[col0 + tid];
        colp[1][tid] = gw[col0 + tid];
        colp[2][tid] = betaw[col0 + tid];
        colp[3][tid] = (MODE == 0) ? g_qbuf[b * 1024 + col0 + tid] : 0.f;
    }

    const int ar0 = tid >> 2,          ak0 = (tid & 3) << 2;
    const int ar1 = (tid + 256) >> 2,  ak1 = ((tid + 256) & 3) << 2;
    const int br0 = tid >> 5,          bc0 = (tid & 31) << 2;
    const int br1 = (tid + 256) >> 5,  bc1 = ((tid + 256) & 31) << 2;
    const float* Aptr = A + (size_t)row0 * 1024;

    float4 pa0, pa1, pb0, pb1;
    auto loadRegs = [&](int k0) {
        pa0 = *(const float4*)(Aptr + (size_t)ar0 * 1024 + k0 + ak0);
        pa1 = *(const float4*)(Aptr + (size_t)ar1 * 1024 + k0 + ak1);
        pb0 = *(const float4*)(W + (size_t)(k0 + br0) * 1024 + col0 + bc0);
        pb1 = *(const float4*)(W + (size_t)(k0 + br1) * 1024 + col0 + bc1);
    };
    auto storeSmem = [&]() {
        As[ak0 + 0][ar0] = pa0.x; As[ak0 + 1][ar0] = pa0.y;
        As[ak0 + 2][ar0] = pa0.z; As[ak0 + 3][ar0] = pa0.w;
        As[ak1 + 0][ar1] = pa1.x; As[ak1 + 1][ar1] = pa1.y;
        As[ak1 + 2][ar1] = pa1.z; As[ak1 + 3][ar1] = pa1.w;
        *(float4*)&Bs[br0][bc0] = pb0;
        *(float4*)&Bs[br1][bc1] = pb1;
    };

    float acc[8][8];
#pragma unroll
    for (int i = 0; i < 8; i++)
#pragma unroll
        for (int j = 0; j < 8; j++) acc[i][j] = 0.f;

    loadRegs(0);
    storeSmem();
    __syncthreads();
    for (int kt = 0; kt < 64; kt++) {
        if (kt < 63) loadRegs((kt + 1) * 16);
#pragma unroll
        for (int k = 0; k < 16; k++) {
            float ar[8], br[8];
#pragma unroll
            for (int i = 0; i < 8; i++) ar[i] = As[k][ty * 8 + i];
#pragma unroll
            for (int j = 0; j < 8; j++) br[j] = Bs[k][tx * 8 + j];
#pragma unroll
            for (int i = 0; i < 8; i++)
#pragma unroll
                for (int j = 0; j < 8; j++) acc[i][j] = fmaf(ar[i], br[j], acc[i][j]);
        }
        __syncthreads();
        if (kt < 63) { storeSmem(); __syncthreads(); }
    }

    // ---- fused epilogue: bias + CELU + GroupNorm (+ dot/kn or v2 store) ----
    // Each row of the tile is owned by the 16 lanes sharing ty (a half-warp).
    const int bh = b * 8 + h;
#pragma unroll
    for (int i = 0; i < 8; i++) {
        const int r = row0 + ty * 8 + i;
        const int m = r & 1023;
        float v[8], s = 0.f, s2 = 0.f;
#pragma unroll
        for (int j = 0; j < 8; j++) {
            float y = acc[i][j] + colp[0][tx * 8 + j];
            y = celu_f(y);
            v[j] = y; s += y; s2 = fmaf(y, y, s2);
        }
#pragma unroll
        for (int o = 8; o; o >>= 1) {
            s  += __shfl_xor_sync(0xffffffffu, s,  o);
            s2 += __shfl_xor_sync(0xffffffffu, s2, o);
        }
        const float mu   = s * (1.f / 128.f);
        const float rstd = rsqrtf(s2 * (1.f / 128.f) - mu * mu + GNEPS);
        if (MODE == 0) {
            float dp = 0.f, k2 = 0.f;
#pragma unroll
            for (int j = 0; j < 8; j++) {
                const int c = tx * 8 + j;
                const float val = (v[j] - mu) * rstd * colp[1][c] + colp[2][c];
                dp = fmaf(val, colp[3][c], dp);
                k2 = fmaf(val, val, k2);
            }
#pragma unroll
            for (int o = 8; o; o >>= 1) {
                dp += __shfl_xor_sync(0xffffffffu, dp, o);
                k2 += __shfl_xor_sync(0xffffffffu, k2, o);
            }
            if (tx == 0) {
                g_dotb[bh * 1024 + m] = dp;
                g_knb[bh * 1024 + m]  = sqrtf(k2);
            }
        } else {
            float o0[8];
#pragma unroll
            for (int j = 0; j < 8; j++) {
                const int c = tx * 8 + j;
                o0[j] = (v[j] - mu) * rstd * colp[1][c] + colp[2][c];
            }
            float* dst = g_v2s + ((size_t)bh * 1024 + m) * 128 + tx * 8;
            ((float4*)dst)[0] = make_float4(o0[0], o0[1], o0[2], o0[3]);
            ((float4*)dst)[1] = make_float4(o0[4], o0[5], o0[6], o0[7]);
        }
    }
}

// ---------------- attention / pooling / output -------------------------------
__device__ __forceinline__ float blockSum128(float v) {
    __shared__ float sh[4];
#pragma unroll
    for (int o = 16; o; o >>= 1) v += __shfl_xor_sync(0xffffffffu, v, o);
    if ((threadIdx.x & 31) == 0) sh[threadIdx.x >> 5] = v;
    __syncthreads();
    v = sh[0] + sh[1] + sh[2] + sh[3];
    __syncthreads();
    return v;
}
__device__ __forceinline__ float blockMax128(float v) {
    __shared__ float sh[4];
#pragma unroll
    for (int o = 16; o; o >>= 1) v = fmaxf(v, __shfl_xor_sync(0xffffffffu, v, o));
    if ((threadIdx.x & 31) == 0) sh[threadIdx.x >> 5] = v;
    __syncthreads();
    v = fmaxf(fmaxf(sh[0], sh[1]), fmaxf(sh[2], sh[3]));
    __syncthreads();
    return v;
}

// grid = B*H = 512 blocks, 128 threads; block handles one (b,h).
__global__ __launch_bounds__(128) void attn_kernel(
    const float* __restrict__ mask,
    const float* __restrict__ W1,  const float* __restrict__ b1,
    const float* __restrict__ Wl,  const float* __restrict__ bl,
    const float* __restrict__ Wl2, const float* __restrict__ bl2,
    float* __restrict__ out)
{
    __shared__ float qdir[128], u[64], b1s[64], wls[64], pool[64];
    __shared__ float cosv[1024], aspv[1024], maskv[1024];

    const int bh  = blockIdx.x;
    const int b   = bh >> 3;
    const int tid = threadIdx.x;

    // q norm + direction
    const float qv = g_qbuf[bh * 128 + tid];
    const float qn = sqrtf(blockSum128(qv * qv));
    qdir[tid] = qv / fmaxf(qn, 1e-12f);
    if (tid < 64) { b1s[tid] = b1[tid]; wls[tid] = Wl[tid]; }
    __syncthreads();

    // u = q_dir @ W1   (score @ W1 == cos * u, since score = cos * q_dir)
    if (tid < 64) {
        float a = 0.f;
#pragma unroll 4
        for (int d = 0; d < 128; d++) a = fmaf(qdir[d], W1[d * 64 + tid], a);
        u[tid] = a;
    }
    __syncthreads();

    const float qnc = fmaxf(qn, 1e-8f);
    const float bl0 = bl[0];

    // phase 1: cos, spatial logits, mask
    float lmax = -1e30f, msum = 0.f;
#pragma unroll
    for (int mi = 0; mi < 8; mi++) {
        const int m = tid + mi * 128;
        const float kn = g_knb[bh * 1024 + m];
        const float cs = g_dotb[bh * 1024 + m] / (qnc * fmaxf(kn, 1e-8f));
        cosv[m] = cs;
        const float mk = mask[b * 1024 + m];
        maskv[m] = mk;
        msum += mk;
        float lg = bl0;
#pragma unroll 8
        for (int j = 0; j < 64; j++)
            lg = fmaf(fmaxf(fmaf(cs, u[j], b1s[j]), 0.f), wls[j], lg);
        if (mk == 0.f) lg = -1e9f;
        aspv[m] = lg;
        lmax = fmaxf(lmax, lg);
    }
    lmax = blockMax128(lmax);
    msum = blockSum128(msum);

    // softmax (unnormalized exps; denominator folded into v2o)
    float esum = 0.f;
#pragma unroll
    for (int mi = 0; mi < 8; mi++) {
        const int m = tid + mi * 128;
        const float e = expf(aspv[m] - lmax);
        aspv[m] = e;
        esum += e;
    }
    esum = blockSum128(esum);
    const float inv = 1.f / esum;
    __syncthreads();

    // pool (channel attention input): mean over masked m of relu(cos*u + b1)
    if (tid < 64) {
        const float uj = u[tid], bj = b1s[tid];
        float p = 0.f;
#pragma unroll 8
        for (int m = 0; m < 1024; m++)
            p = fmaf(fmaxf(fmaf(cosv[m], uj, bj), 0.f), maskv[m], p);
        pool[tid] = p / msum;
    }
    __syncthreads();

    // channel gate
    float a2 = bl2[tid];
#pragma unroll 8
    for (int j = 0; j < 64; j++) a2 = fmaf(pool[j], Wl2[j * 128 + tid], a2);
    const float ach = 1.f / (1.f + expf(-a2));

    // v2o = softmax . v2   (coalesced: lane = channel)
    const float* vb = g_v2s + (size_t)bh * 1024 * 128 + tid;
    float acc = 0.f;
#pragma unroll 8
    for (int m = 0; m < 1024; m++) acc = fmaf(aspv[m], vb[(size_t)m * 128], acc);
    acc *= inv;

    out[bh * 128 + tid] = g_v1buf[bh * 128 + tid] * acc * ach;
}

// ---------------- launch ------------------------------------------------------
extern "C" void kernel_launch(void* const* d_in, const int* in_sizes, int n_in,
                              void* d_out, int out_size) {
    const float* query   = (const float*)d_in[0];
    const float* key     = (const float*)d_in[1];
    const float* mask    = (const float*)d_in[2];
    const float* value1  = (const float*)d_in[3];
    const float* value2  = (const float*)d_in[4];
    const float* W_q     = (const float*)d_in[5];
    const float* b_q     = (const float*)d_in[6];
    const float* g_q     = (const float*)d_in[7];
    const float* beta_q  = (const float*)d_in[8];
    const float* W_k     = (const float*)d_in[9];
    const float* b_k     = (const float*)d_in[10];
    const float* g_k     = (const float*)d_in[11];
    const float* beta_k  = (const float*)d_in[12];
    const float* W_v1    = (const float*)d_in[13];
    const float* b_v1    = (const float*)d_in[14];
    const float* g_v1    = (const float*)d_in[15];
    const float* beta_v1 = (const float*)d_in[16];
    const float* W_v2    = (const float*)d_in[17];
    const float* b_v2    = (const float*)d_in[18];
    const float* g_v2    = (const float*)d_in[19];
    const float* beta_v2 = (const float*)d_in[20];
    const float* W1      = (const float*)d_in[21];
    const float* b1      = (const float*)d_in[22];
    const float* Wl      = (const float*)d_in[23];
    const float* bl      = (const float*)d_in[24];
    const float* Wl2     = (const float*)d_in[25];
    const float* bl2     = (const float*)d_in[26];
    float* out = (float*)d_out;

    small_proj_kernel<0><<<512, 128>>>(query,  W_q,  b_q,  g_q,  beta_q);
    small_proj_kernel<1><<<512, 128>>>(value1, W_v1, b_v1, g_v1, beta_v1);
    big_proj_kernel<0><<<dim3(8, 512), 256>>>(key,    W_k,  b_k,  g_k,  beta_k);
    big_proj_kernel<1><<<dim3(8, 512), 256>>>(value2, W_v2, b_v2, g_v2, beta_v2);
    attn_kernel<<<512, 128>>>(mask, W1, b1, Wl, bl, Wl2, bl2, out);
}

// round 5
// speedup vs baseline: 1.1704x; 1.1704x over previous
#include <cuda_runtime.h>
#include <cuda_bf16.h>
#include <math.h>
#include <stdint.h>

#define ALPHA 1.3f
#define GNEPS 1e-5f
// B=64, M=1024, D=1024, H=8, HD=128

// ---------------- scratch (__device__ globals; SAME set as passing R1) -------
__device__ float g_qbuf[64 * 1024];            // projected q
__device__ float g_v1buf[64 * 1024];           // projected v1
__device__ float g_dotb[64 * 8 * 1024];        // q . k
__device__ float g_knb[64 * 8 * 1024];         // ||k||
__device__ float g_v2s[67108864];              // v2 projected, ((b*8+h)*1024+m)*128+c

__device__ __forceinline__ float celu_f(float x) {
    return x > 0.f ? x : ALPHA * expm1f(x * (1.0f / ALPHA));
}

// ---------------- PTX helpers ------------------------------------------------
__device__ __forceinline__ uint32_t smem_u32(const void* p) {
    return (uint32_t)__cvta_generic_to_shared(p);
}
__device__ __forceinline__ void ldsm4(uint32_t* d, uint32_t addr) {
    asm volatile("ldmatrix.sync.aligned.m8n8.x4.shared.b16 {%0,%1,%2,%3}, [%4];"
                 : "=r"(d[0]), "=r"(d[1]), "=r"(d[2]), "=r"(d[3]) : "r"(addr));
}
__device__ __forceinline__ void mma16816(float* c, const uint32_t* a,
                                         uint32_t b0, uint32_t b1) {
    asm volatile(
        "mma.sync.aligned.m16n8k16.row.col.f32.bf16.bf16.f32 "
        "{%0,%1,%2,%3}, {%4,%5,%6,%7}, {%8,%9}, {%0,%1,%2,%3};"
        : "+f"(c[0]), "+f"(c[1]), "+f"(c[2]), "+f"(c[3])
        : "r"(a[0]), "r"(a[1]), "r"(a[2]), "r"(a[3]), "r"(b0), "r"(b1));
}
__device__ __forceinline__ float quad2(float v) {
    v += __shfl_xor_sync(0xffffffffu, v, 1);
    v += __shfl_xor_sync(0xffffffffu, v, 2);
    return v;
}
// pack 4 floats -> 4 bf16 (hi) in a uint2
__device__ __forceinline__ uint2 pack_hi4(float4 v, float4& rem) {
    __nv_bfloat16 h0 = __float2bfloat16(v.x), h1 = __float2bfloat16(v.y);
    __nv_bfloat16 h2 = __float2bfloat16(v.z), h3 = __float2bfloat16(v.w);
    rem.x = v.x - __bfloat162float(h0);
    rem.y = v.y - __bfloat162float(h1);
    rem.z = v.z - __bfloat162float(h2);
    rem.w = v.w - __bfloat162float(h3);
    __nv_bfloat162 p01; p01.x = h0; p01.y = h1;
    __nv_bfloat162 p23; p23.x = h2; p23.y = h3;
    uint2 r;
    r.x = *(uint32_t*)&p01;
    r.y = *(uint32_t*)&p23;
    return r;
}
__device__ __forceinline__ uint2 pack_lo4(float4 rem) {
    __nv_bfloat162 p01; p01.x = __float2bfloat16(rem.x); p01.y = __float2bfloat16(rem.y);
    __nv_bfloat162 p23; p23.x = __float2bfloat16(rem.z); p23.y = __float2bfloat16(rem.w);
    uint2 r;
    r.x = *(uint32_t*)&p01;
    r.y = *(uint32_t*)&p23;
    return r;
}

// ---------------- small projections: q, v1 (proven in R1) --------------------
template <int DST>
__global__ __launch_bounds__(128) void small_proj_kernel(
    const float* __restrict__ X, const float* __restrict__ W,
    const float* __restrict__ bias, const float* __restrict__ gw,
    const float* __restrict__ betaw)
{
    __shared__ float xs[1024];
    __shared__ float rs[4], rs2[4];
    const int row = blockIdx.x >> 3;
    const int h   = blockIdx.x & 7;
    const int c   = threadIdx.x;

    const float4* xr = (const float4*)(X + (size_t)row * 1024);
    float4* xs4 = (float4*)xs;
    for (int i = c; i < 256; i += 128) xs4[i] = xr[i];
    __syncthreads();

    const int col = h * 128 + c;
    float acc = bias[col];
    const float* Wp = W + col;
#pragma unroll 8
    for (int k = 0; k < 1024; k++) acc = fmaf(xs[k], Wp[(size_t)k * 1024], acc);
    acc = celu_f(acc);

    float s = acc, s2 = acc * acc;
#pragma unroll
    for (int o = 16; o; o >>= 1) {
        s  += __shfl_xor_sync(0xffffffffu, s,  o);
        s2 += __shfl_xor_sync(0xffffffffu, s2, o);
    }
    if ((c & 31) == 0) { rs[c >> 5] = s; rs2[c >> 5] = s2; }
    __syncthreads();
    s  = rs[0] + rs[1] + rs[2] + rs[3];
    s2 = rs2[0] + rs2[1] + rs2[2] + rs2[3];
    const float mu   = s * (1.f / 128.f);
    const float rstd = rsqrtf(s2 * (1.f / 128.f) - mu * mu + GNEPS);
    const float v = (acc - mu) * rstd * gw[col] + betaw[col];
    if (DST == 0) g_qbuf[row * 1024 + col] = v;
    else          g_v1buf[row * 1024 + col] = v;
}

// ---------------- tensor-core big projection GEMM ----------------------------
// grid (8 heads, 512 row-tiles), 256 thr = 8 warps (4M x 2N). CTA tile 128x128.
// Reads fp32 A (key/value2) and W directly; converts to bf16 hi/lo in-kernel.
// Per K=32 chunk: 3 compensated passes Ahi*Bhi + Ahi*Blo + Alo*Bhi (fp32 acc).
// Padded smem (row stride 40 halves = 80B): ldmatrix conflict-free, no swizzle.
template <int MODE>
__global__ __launch_bounds__(256) void big_mma_kernel(
    const float* __restrict__ A, const float* __restrict__ W,
    const float* __restrict__ bias, const float* __restrict__ gw,
    const float* __restrict__ betaw)
{
    __shared__ __align__(16) __nv_bfloat16 sAhi[128][40];
    __shared__ __align__(16) __nv_bfloat16 sAlo[128][40];
    __shared__ __align__(16) __nv_bfloat16 sBhi[128][40];   // [n][k]
    __shared__ __align__(16) __nv_bfloat16 sBlo[128][40];
    __shared__ float sbias[128], sg[128], sbeta[128], sq[128];
    __shared__ float psum[128][2], psum2[128][2];
    __shared__ float pdot[128][2], pk2[128][2];

    const int h    = blockIdx.x;
    const int tm   = blockIdx.y;
    const int tid  = threadIdx.x;
    const int lane = tid & 31;
    const int warp = tid >> 5;
    const int wm   = warp >> 1;        // 0..3
    const int wn   = warp & 1;         // 0..1
    const int col0 = h * 128;
    const int b0   = tm >> 3;

    if (tid < 128) {
        sbias[tid] = bias[col0 + tid];
        sg[tid]    = gw[col0 + tid];
        sbeta[tid] = betaw[col0 + tid];
        sq[tid]    = (MODE == 0) ? g_qbuf[b0 * 1024 + col0 + tid] : 0.f;
    }

    // ---- global load assignments (fp32) ----
    const int ar  = tid >> 1;            // A row 0..127
    const int ac4 = (tid & 1) * 4;       // A float4 col base (of 8 per row)
    const int bk  = tid >> 3;            // B k-row 0..31
    const int bn4 = (tid & 7) * 4;       // B float4 n base (of 32 per k-row)

    const float* Abase = A + (size_t)(tm * 128 + ar) * 1024;
    const float* Wbase = W + (size_t)bk * 1024 + col0;

    float4 pfA[4], pfB[4];
    auto prefetch = [&](int kc) {
        const float4* Ap = (const float4*)(Abase + kc * 32) + ac4;
#pragma unroll
        for (int i = 0; i < 4; i++) pfA[i] = Ap[i];
        const float4* Wp = (const float4*)(Wbase + (size_t)kc * 32 * 1024) + bn4;
#pragma unroll
        for (int i = 0; i < 4; i++) pfB[i] = Wp[i];
    };
    auto store_smem = [&]() {
#pragma unroll
        for (int i = 0; i < 4; i++) {
            const int k0 = (ac4 + i) * 4;
            float4 rem;
            const uint2 hi = pack_hi4(pfA[i], rem);
            const uint2 lo = pack_lo4(rem);
            *(uint2*)&sAhi[ar][k0] = hi;
            *(uint2*)&sAlo[ar][k0] = lo;
        }
#pragma unroll
        for (int i = 0; i < 4; i++) {
            const int n0 = (bn4 + i) * 4;
            const float xs[4] = {pfB[i].x, pfB[i].y, pfB[i].z, pfB[i].w};
#pragma unroll
            for (int j = 0; j < 4; j++) {
                const __nv_bfloat16 hv = __float2bfloat16(xs[j]);
                sBhi[n0 + j][bk] = hv;
                sBlo[n0 + j][bk] = __float2bfloat16(xs[j] - __bfloat162float(hv));
            }
        }
    };

    // ---- ldmatrix addressing (padded stride 80B, no swizzle) ----
    const uint32_t aHi = smem_u32(sAhi), aLo = smem_u32(sAlo);
    const uint32_t bHi = smem_u32(sBhi), bLo = smem_u32(sBlo);
    const uint32_t klane = (uint32_t)(((lane >> 4) & 1) * 16);   // byte col 0/16
    uint32_t aoff[2];
#pragma unroll
    for (int mt = 0; mt < 2; mt++) {
        const int r = wm * 32 + mt * 16 + (lane & 7) + 8 * ((lane >> 3) & 1);
        aoff[mt] = (uint32_t)r * 80u;
    }
    uint32_t boff[4];
#pragma unroll
    for (int bp = 0; bp < 4; bp++) {
        const int n = wn * 64 + bp * 16 + (lane & 7) + 8 * ((lane >> 3) & 1);
        boff[bp] = (uint32_t)n * 80u;
    }

    float acc[2][8][4];
#pragma unroll
    for (int mt = 0; mt < 2; mt++)
#pragma unroll
        for (int nf = 0; nf < 8; nf++)
#pragma unroll
            for (int q = 0; q < 4; q++) acc[mt][nf][q] = 0.f;

    prefetch(0);
    for (int kc = 0; kc < 32; kc++) {
        __syncthreads();            // previous compute finished reading smem
        store_smem();
        __syncthreads();
        if (kc < 31) prefetch(kc + 1);   // LDGs land during compute below

#pragma unroll
        for (int s = 0; s < 2; s++) {
            const uint32_t col = klane + (uint32_t)s * 32u;
            uint32_t ah[2][4], al[2][4];
#pragma unroll
            for (int mt = 0; mt < 2; mt++) {
                ldsm4(ah[mt], aHi + aoff[mt] + col);
                ldsm4(al[mt], aLo + aoff[mt] + col);
            }
#pragma unroll
            for (int bp = 0; bp < 4; bp++) {
                uint32_t bh[4], bl[4];
                ldsm4(bh, bHi + boff[bp] + col);
                ldsm4(bl, bLo + boff[bp] + col);
#pragma unroll
                for (int mt = 0; mt < 2; mt++) {
                    mma16816(acc[mt][2 * bp],     ah[mt], bh[0], bh[2]);
                    mma16816(acc[mt][2 * bp + 1], ah[mt], bh[1], bh[3]);
                    mma16816(acc[mt][2 * bp],     ah[mt], bl[0], bl[2]);
                    mma16816(acc[mt][2 * bp + 1], ah[mt], bl[1], bl[3]);
                    mma16816(acc[mt][2 * bp],     al[mt], bh[0], bh[2]);
                    mma16816(acc[mt][2 * bp + 1], al[mt], bh[1], bh[3]);
                }
            }
        }
    }

    // ---- register epilogue: CELU, per-row GroupNorm, fused reductions ----
    const int bh = b0 * 8 + h;
#pragma unroll
    for (int mt = 0; mt < 2; mt++)
#pragma unroll
        for (int nf = 0; nf < 8; nf++) {
            const int c = wn * 64 + nf * 8 + 2 * (lane & 3);
            acc[mt][nf][0] = celu_f(acc[mt][nf][0] + sbias[c]);
            acc[mt][nf][1] = celu_f(acc[mt][nf][1] + sbias[c + 1]);
            acc[mt][nf][2] = celu_f(acc[mt][nf][2] + sbias[c]);
            acc[mt][nf][3] = celu_f(acc[mt][nf][3] + sbias[c + 1]);
        }

#pragma unroll
    for (int mt = 0; mt < 2; mt++) {
        float sA = 0.f, s2A = 0.f, sB = 0.f, s2B = 0.f;
#pragma unroll
        for (int nf = 0; nf < 8; nf++) {
            sA += acc[mt][nf][0] + acc[mt][nf][1];
            s2A = fmaf(acc[mt][nf][0], acc[mt][nf][0], fmaf(acc[mt][nf][1], acc[mt][nf][1], s2A));
            sB += acc[mt][nf][2] + acc[mt][nf][3];
            s2B = fmaf(acc[mt][nf][2], acc[mt][nf][2], fmaf(acc[mt][nf][3], acc[mt][nf][3], s2B));
        }
        sA = quad2(sA); s2A = quad2(s2A); sB = quad2(sB); s2B = quad2(s2B);
        if ((lane & 3) == 0) {
            const int R = wm * 32 + mt * 16 + (lane >> 2);
            psum[R][wn] = sA;      psum2[R][wn] = s2A;
            psum[R + 8][wn] = sB;  psum2[R + 8][wn] = s2B;
        }
    }
    __syncthreads();

    float mu_[2][2], rs_[2][2];
#pragma unroll
    for (int mt = 0; mt < 2; mt++)
#pragma unroll
        for (int hf = 0; hf < 2; hf++) {
            const int R = wm * 32 + mt * 16 + (lane >> 2) + 8 * hf;
            const float S  = psum[R][0] + psum[R][1];
            const float S2 = psum2[R][0] + psum2[R][1];
            const float mu = S * (1.f / 128.f);
            mu_[mt][hf] = mu;
            rs_[mt][hf] = rsqrtf(S2 * (1.f / 128.f) - mu * mu + GNEPS);
        }

    if (MODE == 0) {
#pragma unroll
        for (int mt = 0; mt < 2; mt++) {
            float dpA = 0.f, k2A = 0.f, dpB = 0.f, k2B = 0.f;
#pragma unroll
            for (int nf = 0; nf < 8; nf++) {
                const int c = wn * 64 + nf * 8 + 2 * (lane & 3);
                float v0 = (acc[mt][nf][0] - mu_[mt][0]) * rs_[mt][0] * sg[c]     + sbeta[c];
                float v1 = (acc[mt][nf][1] - mu_[mt][0]) * rs_[mt][0] * sg[c + 1] + sbeta[c + 1];
                float v2 = (acc[mt][nf][2] - mu_[mt][1]) * rs_[mt][1] * sg[c]     + sbeta[c];
                float v3 = (acc[mt][nf][3] - mu_[mt][1]) * rs_[mt][1] * sg[c + 1] + sbeta[c + 1];
                dpA = fmaf(v0, sq[c], fmaf(v1, sq[c + 1], dpA));
                k2A = fmaf(v0, v0, fmaf(v1, v1, k2A));
                dpB = fmaf(v2, sq[c], fmaf(v3, sq[c + 1], dpB));
                k2B = fmaf(v2, v2, fmaf(v3, v3, k2B));
            }
            dpA = quad2(dpA); k2A = quad2(k2A); dpB = quad2(dpB); k2B = quad2(k2B);
            if ((lane & 3) == 0) {
                const int R = wm * 32 + mt * 16 + (lane >> 2);
                pdot[R][wn] = dpA;      pk2[R][wn] = k2A;
                pdot[R + 8][wn] = dpB;  pk2[R + 8][wn] = k2B;
            }
        }
        __syncthreads();
        if (wn == 0 && (lane & 3) == 0) {
#pragma unroll
            for (int mt = 0; mt < 2; mt++)
#pragma unroll
                for (int hf = 0; hf < 2; hf++) {
                    const int R = wm * 32 + mt * 16 + (lane >> 2) + 8 * hf;
                    const int m = (tm * 128 + R) & 1023;
                    g_dotb[bh * 1024 + m] = pdot[R][0] + pdot[R][1];
                    g_knb[bh * 1024 + m]  = sqrtf(pk2[R][0] + pk2[R][1]);
                }
        }
    } else {
#pragma unroll
        for (int mt = 0; mt < 2; mt++)
#pragma unroll
            for (int hf = 0; hf < 2; hf++) {
                const int R = wm * 32 + mt * 16 + (lane >> 2) + 8 * hf;
                const int m = (tm * 128 + R) & 1023;
                float* dst = g_v2s + ((size_t)bh * 1024 + m) * 128;
                const float mu = mu_[mt][hf], rstd = rs_[mt][hf];
#pragma unroll
                for (int nf = 0; nf < 8; nf++) {
                    const int c = wn * 64 + nf * 8 + 2 * (lane & 3);
                    const float v0 = (acc[mt][nf][2 * hf]     - mu) * rstd * sg[c]     + sbeta[c];
                    const float v1 = (acc[mt][nf][2 * hf + 1] - mu) * rstd * sg[c + 1] + sbeta[c + 1];
                    *(float2*)(dst + c) = make_float2(v0, v1);
                }
            }
    }
}

// ---------------- attention / pooling / output (proven in R1) ----------------
__device__ __forceinline__ float blockSum128(float v) {
    __shared__ float sh[4];
#pragma unroll
    for (int o = 16; o; o >>= 1) v += __shfl_xor_sync(0xffffffffu, v, o);
    if ((threadIdx.x & 31) == 0) sh[threadIdx.x >> 5] = v;
    __syncthreads();
    v = sh[0] + sh[1] + sh[2] + sh[3];
    __syncthreads();
    return v;
}
__device__ __forceinline__ float blockMax128(float v) {
    __shared__ float sh[4];
#pragma unroll
    for (int o = 16; o; o >>= 1) v = fmaxf(v, __shfl_xor_sync(0xffffffffu, v, o));
    if ((threadIdx.x & 31) == 0) sh[threadIdx.x >> 5] = v;
    __syncthreads();
    v = fmaxf(fmaxf(sh[0], sh[1]), fmaxf(sh[2], sh[3]));
    __syncthreads();
    return v;
}

__global__ __launch_bounds__(128) void attn_kernel(
    const float* __restrict__ mask,
    const float* __restrict__ W1,  const float* __restrict__ b1,
    const float* __restrict__ Wl,  const float* __restrict__ bl,
    const float* __restrict__ Wl2, const float* __restrict__ bl2,
    float* __restrict__ out)
{
    __shared__ float qdir[128], u[64], b1s[64], wls[64], pool[64];
    __shared__ float cosv[1024], aspv[1024], maskv[1024];

    const int bh  = blockIdx.x;
    const int b   = bh >> 3;
    const int tid = threadIdx.x;

    const float qv = g_qbuf[bh * 128 + tid];
    const float qn = sqrtf(blockSum128(qv * qv));
    qdir[tid] = qv / fmaxf(qn, 1e-12f);
    if (tid < 64) { b1s[tid] = b1[tid]; wls[tid] = Wl[tid]; }
    __syncthreads();

    if (tid < 64) {
        float a = 0.f;
#pragma unroll 4
        for (int d = 0; d < 128; d++) a = fmaf(qdir[d], W1[d * 64 + tid], a);
        u[tid] = a;
    }
    __syncthreads();

    const float qnc = fmaxf(qn, 1e-8f);
    const float bl0 = bl[0];

    float lmax = -1e30f, msum = 0.f;
#pragma unroll
    for (int mi = 0; mi < 8; mi++) {
        const int m = tid + mi * 128;
        const float kn = g_knb[bh * 1024 + m];
        const float cs = g_dotb[bh * 1024 + m] / (qnc * fmaxf(kn, 1e-8f));
        cosv[m] = cs;
        const float mk = mask[b * 1024 + m];
        maskv[m] = mk;
        msum += mk;
        float lg = bl0;
#pragma unroll 8
        for (int j = 0; j < 64; j++)
            lg = fmaf(fmaxf(fmaf(cs, u[j], b1s[j]), 0.f), wls[j], lg);
        if (mk == 0.f) lg = -1e9f;
        aspv[m] = lg;
        lmax = fmaxf(lmax, lg);
    }
    lmax = blockMax128(lmax);
    msum = blockSum128(msum);

    float esum = 0.f;
#pragma unroll
    for (int mi = 0; mi < 8; mi++) {
        const int m = tid + mi * 128;
        const float e = expf(aspv[m] - lmax);
        aspv[m] = e;
        esum += e;
    }
    esum = blockSum128(esum);
    const float inv = 1.f / esum;
    __syncthreads();

    if (tid < 64) {
        const float uj = u[tid], bj = b1s[tid];
        float p = 0.f;
#pragma unroll 8
        for (int m = 0; m < 1024; m++)
            p = fmaf(fmaxf(fmaf(cosv[m], uj, bj), 0.f), maskv[m], p);
        pool[tid] = p / msum;
    }
    __syncthreads();

    float a2 = bl2[tid];
#pragma unroll 8
    for (int j = 0; j < 64; j++) a2 = fmaf(pool[j], Wl2[j * 128 + tid], a2);
    const float ach = 1.f / (1.f + expf(-a2));

    const float* vb = g_v2s + (size_t)bh * 1024 * 128 + tid;
    float acc = 0.f;
#pragma unroll 8
    for (int m = 0; m < 1024; m++) acc = fmaf(aspv[m], vb[(size_t)m * 128], acc);
    acc *= inv;

    out[bh * 128 + tid] = g_v1buf[bh * 128 + tid] * acc * ach;
}

// ---------------- launch ------------------------------------------------------
extern "C" void kernel_launch(void* const* d_in, const int* in_sizes, int n_in,
                              void* d_out, int out_size) {
    const float* query   = (const float*)d_in[0];
    const float* key     = (const float*)d_in[1];
    const float* mask    = (const float*)d_in[2];
    const float* value1  = (const float*)d_in[3];
    const float* value2  = (const float*)d_in[4];
    const float* W_q     = (const float*)d_in[5];
    const float* b_q     = (const float*)d_in[6];
    const float* g_q     = (const float*)d_in[7];
    const float* beta_q  = (const float*)d_in[8];
    const float* W_k     = (const float*)d_in[9];
    const float* b_k     = (const float*)d_in[10];
    const float* g_k     = (const float*)d_in[11];
    const float* beta_k  = (const float*)d_in[12];
    const float* W_v1    = (const float*)d_in[13];
    const float* b_v1    = (const float*)d_in[14];
    const float* g_v1    = (const float*)d_in[15];
    const float* beta_v1 = (const float*)d_in[16];
    const float* W_v2    = (const float*)d_in[17];
    const float* b_v2    = (const float*)d_in[18];
    const float* g_v2    = (const float*)d_in[19];
    const float* beta_v2 = (const float*)d_in[20];
    const float* W1      = (const float*)d_in[21];
    const float* b1      = (const float*)d_in[22];
    const float* Wl      = (const float*)d_in[23];
    const float* bl      = (const float*)d_in[24];
    const float* Wl2     = (const float*)d_in[25];
    const float* bl2     = (const float*)d_in[26];
    float* out = (float*)d_out;

    small_proj_kernel<0><<<512, 128>>>(query,  W_q,  b_q,  g_q,  beta_q);
    small_proj_kernel<1><<<512, 128>>>(value1, W_v1, b_v1, g_v1, beta_v1);

    big_mma_kernel<0><<<dim3(8, 512), 256>>>(key,    W_k,  b_k,  g_k,  beta_k);
    big_mma_kernel<1><<<dim3(8, 512), 256>>>(value2, W_v2, b_v2, g_v2, beta_v2);

    attn_kernel<<<512, 128>>>(mask, W1, b1, Wl, bl, Wl2, bl2, out);
}

// round 6
// speedup vs baseline: 2.2745x; 1.9434x over previous
#include <cuda_runtime.h>
#include <cuda_bf16.h>
#include <math.h>
#include <stdint.h>

#define ALPHA 1.3f
#define GNEPS 1e-5f
// B=64, M=1024, D=1024, H=8, HD=128

// ---------------- scratch (__device__ globals) -------------------------------
__device__ float g_qbuf[64 * 1024];
__device__ float g_v1buf[64 * 1024];
__device__ float g_dotb[64 * 8 * 1024];
__device__ float g_knb[64 * 8 * 1024];
__device__ float g_v2s[67108864];              // ((b*8+h)*1024+m)*128+c

// Pre-converted W^T tiles: [mode][ (h*64+kc)*128 + n ]*24 + k  (k16 chunks, pad 24)
__device__ __nv_bfloat16 g_Bhi[2][1572864];    // 3MB each
__device__ __nv_bfloat16 g_Blo[2][1572864];

__device__ __forceinline__ float celu_f(float x) {
    return x > 0.f ? x : ALPHA * expm1f(x * (1.0f / ALPHA));
}

// ---------------- PTX helpers ------------------------------------------------
__device__ __forceinline__ uint32_t smem_u32(const void* p) {
    return (uint32_t)__cvta_generic_to_shared(p);
}
__device__ __forceinline__ void cp16(uint32_t dst, const void* src) {
    asm volatile("cp.async.cg.shared.global [%0], [%1], 16;\n"
                 :: "r"(dst), "l"(__cvta_generic_to_global(src)));
}
#define CP_COMMIT()  asm volatile("cp.async.commit_group;\n" ::: "memory")
#define CP_WAIT1()   asm volatile("cp.async.wait_group 1;\n" ::: "memory")
#define CP_WAIT0()   asm volatile("cp.async.wait_group 0;\n" ::: "memory")

__device__ __forceinline__ void ldsm4(uint32_t* d, uint32_t addr) {
    asm volatile("ldmatrix.sync.aligned.m8n8.x4.shared.b16 {%0,%1,%2,%3}, [%4];"
                 : "=r"(d[0]), "=r"(d[1]), "=r"(d[2]), "=r"(d[3]) : "r"(addr));
}
__device__ __forceinline__ void mma16816(float* c, const uint32_t* a,
                                         uint32_t b0, uint32_t b1) {
    asm volatile(
        "mma.sync.aligned.m16n8k16.row.col.f32.bf16.bf16.f32 "
        "{%0,%1,%2,%3}, {%4,%5,%6,%7}, {%8,%9}, {%0,%1,%2,%3};"
        : "+f"(c[0]), "+f"(c[1]), "+f"(c[2]), "+f"(c[3])
        : "r"(a[0]), "r"(a[1]), "r"(a[2]), "r"(a[3]), "r"(b0), "r"(b1));
}
__device__ __forceinline__ float quad2(float v) {
    v += __shfl_xor_sync(0xffffffffu, v, 1);
    v += __shfl_xor_sync(0xffffffffu, v, 2);
    return v;
}
// pack 8 floats -> 8 bf16 (hi) + residuals
__device__ __forceinline__ uint4 pack_hi8(const float* v, float* rem) {
    __nv_bfloat16 h[8];
#pragma unroll
    for (int i = 0; i < 8; i++) {
        h[i] = __float2bfloat16(v[i]);
        rem[i] = v[i] - __bfloat162float(h[i]);
    }
    uint4 r;
    __nv_bfloat162 p;
    p.x = h[0]; p.y = h[1]; r.x = *(uint32_t*)&p;
    p.x = h[2]; p.y = h[3]; r.y = *(uint32_t*)&p;
    p.x = h[4]; p.y = h[5]; r.z = *(uint32_t*)&p;
    p.x = h[6]; p.y = h[7]; r.w = *(uint32_t*)&p;
    return r;
}
__device__ __forceinline__ uint4 pack8(const float* v) {
    uint4 r;
    __nv_bfloat162 p;
    p.x = __float2bfloat16(v[0]); p.y = __float2bfloat16(v[1]); r.x = *(uint32_t*)&p;
    p.x = __float2bfloat16(v[2]); p.y = __float2bfloat16(v[3]); r.y = *(uint32_t*)&p;
    p.x = __float2bfloat16(v[4]); p.y = __float2bfloat16(v[5]); r.z = *(uint32_t*)&p;
    p.x = __float2bfloat16(v[6]); p.y = __float2bfloat16(v[7]); r.w = *(uint32_t*)&p;
    return r;
}

// ---------------- convB: W -> per-head [n][k] bf16 hi/lo padded tiles --------
// grid (64 kc, 8 head), 256 threads. tile row stride 24 halves (48B).
__global__ __launch_bounds__(256) void convB_kernel(const float* __restrict__ W, int mode)
{
    const int kc = blockIdx.x, h = blockIdx.y, tid = threadIdx.x;
    const int n = tid & 127;
    const int kh = (tid >> 7) * 8;     // 0 or 8
    float vals[8], rem[8];
#pragma unroll
    for (int j = 0; j < 8; j++)
        vals[j] = W[(size_t)(kc * 16 + kh + j) * 1024 + h * 128 + n];
    const size_t base = ((size_t)(h * 64 + kc) * 128 + n) * 24 + kh;
    const uint4 hi = pack_hi8(vals, rem);
    const uint4 lo = pack8(rem);
    *(uint4*)&g_Bhi[mode][base] = hi;
    *(uint4*)&g_Blo[mode][base] = lo;
}

// ---------------- small projections: q, v1 (proven) --------------------------
template <int DST>
__global__ __launch_bounds__(128) void small_proj_kernel(
    const float* __restrict__ X, const float* __restrict__ W,
    const float* __restrict__ bias, const float* __restrict__ gw,
    const float* __restrict__ betaw)
{
    __shared__ float xs[1024];
    __shared__ float rs[4], rs2[4];
    const int row = blockIdx.x >> 3;
    const int h   = blockIdx.x & 7;
    const int c   = threadIdx.x;

    const float4* xr = (const float4*)(X + (size_t)row * 1024);
    float4* xs4 = (float4*)xs;
    for (int i = c; i < 256; i += 128) xs4[i] = xr[i];
    __syncthreads();

    const int col = h * 128 + c;
    float acc = bias[col];
    const float* Wp = W + col;
#pragma unroll 8
    for (int k = 0; k < 1024; k++) acc = fmaf(xs[k], Wp[(size_t)k * 1024], acc);
    acc = celu_f(acc);

    float s = acc, s2 = acc * acc;
#pragma unroll
    for (int o = 16; o; o >>= 1) {
        s  += __shfl_xor_sync(0xffffffffu, s,  o);
        s2 += __shfl_xor_sync(0xffffffffu, s2, o);
    }
    if ((c & 31) == 0) { rs[c >> 5] = s; rs2[c >> 5] = s2; }
    __syncthreads();
    s  = rs[0] + rs[1] + rs[2] + rs[3];
    s2 = rs2[0] + rs2[1] + rs2[2] + rs2[3];
    const float mu   = s * (1.f / 128.f);
    const float rstd = rsqrtf(s2 * (1.f / 128.f) - mu * mu + GNEPS);
    const float v = (acc - mu) * rstd * gw[col] + betaw[col];
    if (DST == 0) g_qbuf[row * 1024 + col] = v;
    else          g_v1buf[row * 1024 + col] = v;
}

// ---------------- tensor-core big projection GEMM ----------------------------
// grid (8 heads, 512 row-tiles), 256 thr = 8 warps (4M x 2N). CTA 128x128.
// K-chunk 16 (64 chunks). A: fp32 LDG -> reg convert -> smem (single stage,
// LDG prefetched across compute). B: pre-converted bf16 hi/lo via cp.async,
// double-buffered. 3 compensated passes per chunk. Fused CELU+GN epilogue.
template <int MODE>
__global__ __launch_bounds__(256, 2) void big_mma_kernel(
    const float* __restrict__ A,
    const float* __restrict__ bias, const float* __restrict__ gw,
    const float* __restrict__ betaw)
{
    __shared__ __align__(16) __nv_bfloat16 sAhi[128][24];
    __shared__ __align__(16) __nv_bfloat16 sAlo[128][24];
    __shared__ __align__(16) __nv_bfloat16 sB[2][2][128][24];  // [stage][hi/lo]
    __shared__ float sbias[128], sg[128], sbeta[128], sq[128];
    __shared__ float psum[128][2], psum2[128][2];
    __shared__ float pdot[128][2], pk2[128][2];

    const int h    = blockIdx.x;
    const int tm   = blockIdx.y;
    const int tid  = threadIdx.x;
    const int lane = tid & 31;
    const int warp = tid >> 5;
    const int wm   = warp >> 1;
    const int wn   = warp & 1;
    const int col0 = h * 128;
    const int b0   = tm >> 3;

    if (tid < 128) {
        sbias[tid] = bias[col0 + tid];
        sg[tid]    = gw[col0 + tid];
        sbeta[tid] = betaw[col0 + tid];
        sq[tid]    = (MODE == 0) ? g_qbuf[b0 * 1024 + col0 + tid] : 0.f;
    }

    // ---- A global loads: thread -> (row, half-of-k16) ----
    const int ar = tid >> 1;
    const int ak = (tid & 1) * 8;
    const float* Abase = A + (size_t)(tm * 128 + ar) * 1024 + ak;

    float pf[8];
    auto ldgA = [&](int kc) {
        const float4* p = (const float4*)(Abase + kc * 16);
        *(float4*)&pf[0] = p[0];
        *(float4*)&pf[4] = p[1];
    };
    const uint32_t aHiRow = smem_u32(&sAhi[ar][ak]);
    const uint32_t aLoRow = smem_u32(&sAlo[ar][ak]);
    auto storeA = [&]() {
        float rem[8];
        const uint4 hi = pack_hi8(pf, rem);
        const uint4 lo = pack8(rem);
        *(uint4*)__cvta_shared_to_generic(aHiRow) = hi;
        *(uint4*)__cvta_shared_to_generic(aLoRow) = lo;
    };

    // ---- B cp.async (pre-converted) ----
    const __nv_bfloat16* Bhi = g_Bhi[MODE];
    const __nv_bfloat16* Blo = g_Blo[MODE];
    const uint32_t sB0 = smem_u32(&sB[0][0][0][0]);
    auto cpB = [&](int kc, int stg) {
        const size_t tb = (size_t)(h * 64 + kc) * 3072;   // elements (128*24)
        const uint32_t d = sB0 + (uint32_t)stg * 12288u;
        cp16(d + (uint32_t)tid * 16u, Bhi + tb + (size_t)tid * 8);
        if (tid < 128) cp16(d + (uint32_t)(tid + 256) * 16u, Bhi + tb + (size_t)(tid + 256) * 8);
        cp16(d + 6144u + (uint32_t)tid * 16u, Blo + tb + (size_t)tid * 8);
        if (tid < 128) cp16(d + 6144u + (uint32_t)(tid + 256) * 16u, Blo + tb + (size_t)(tid + 256) * 8);
    };

    // ---- ldmatrix addressing (48B row stride) ----
    const uint32_t aHi = smem_u32(sAhi), aLo = smem_u32(sAlo);
    const uint32_t klane = (uint32_t)(((lane >> 4) & 1) * 16);
    uint32_t aoff[2];
#pragma unroll
    for (int mt = 0; mt < 2; mt++) {
        const int r = wm * 32 + mt * 16 + (lane & 7) + 8 * ((lane >> 3) & 1);
        aoff[mt] = (uint32_t)r * 48u + klane;
    }
    uint32_t boff[4];
#pragma unroll
    for (int bp = 0; bp < 4; bp++) {
        const int n = wn * 64 + bp * 16 + (lane & 7) + 8 * ((lane >> 3) & 1);
        boff[bp] = (uint32_t)n * 48u + klane;
    }

    float acc[2][8][4];
#pragma unroll
    for (int mt = 0; mt < 2; mt++)
#pragma unroll
        for (int nf = 0; nf < 8; nf++)
#pragma unroll
            for (int q = 0; q < 4; q++) acc[mt][nf][q] = 0.f;

    ldgA(0);
    cpB(0, 0);
    CP_COMMIT();

    for (int kc = 0; kc < 64; kc++) {
        storeA();                              // A buffer free (sync at loop end)
        if (kc < 63) { cpB(kc + 1, (kc + 1) & 1); CP_COMMIT(); CP_WAIT1(); }
        else         { CP_WAIT0(); }
        __syncthreads();                       // A stores + B(kc) visible
        if (kc < 63) ldgA(kc + 1);             // overlaps compute

        const uint32_t bbase = sB0 + (uint32_t)(kc & 1) * 12288u;
        uint32_t ah[2][4], al[2][4];
#pragma unroll
        for (int mt = 0; mt < 2; mt++) {
            ldsm4(ah[mt], aHi + aoff[mt]);
            ldsm4(al[mt], aLo + aoff[mt]);
        }
#pragma unroll
        for (int bp = 0; bp < 4; bp++) {
            uint32_t bh[4], bl[4];
            ldsm4(bh, bbase + boff[bp]);
            ldsm4(bl, bbase + 6144u + boff[bp]);
#pragma unroll
            for (int mt = 0; mt < 2; mt++) {
                mma16816(acc[mt][2 * bp],     ah[mt], bh[0], bh[2]);
                mma16816(acc[mt][2 * bp + 1], ah[mt], bh[1], bh[3]);
                mma16816(acc[mt][2 * bp],     ah[mt], bl[0], bl[2]);
                mma16816(acc[mt][2 * bp + 1], ah[mt], bl[1], bl[3]);
                mma16816(acc[mt][2 * bp],     al[mt], bh[0], bh[2]);
                mma16816(acc[mt][2 * bp + 1], al[mt], bh[1], bh[3]);
            }
        }
        __syncthreads();                       // all reads of A smem done
    }

    // ---- register epilogue (proven in R5) ----
    const int bh2 = b0 * 8 + h;
#pragma unroll
    for (int mt = 0; mt < 2; mt++)
#pragma unroll
        for (int nf = 0; nf < 8; nf++) {
            const int c = wn * 64 + nf * 8 + 2 * (lane & 3);
            acc[mt][nf][0] = celu_f(acc[mt][nf][0] + sbias[c]);
            acc[mt][nf][1] = celu_f(acc[mt][nf][1] + sbias[c + 1]);
            acc[mt][nf][2] = celu_f(acc[mt][nf][2] + sbias[c]);
            acc[mt][nf][3] = celu_f(acc[mt][nf][3] + sbias[c + 1]);
        }

#pragma unroll
    for (int mt = 0; mt < 2; mt++) {
        float sA = 0.f, s2A = 0.f, sBv = 0.f, s2B = 0.f;
#pragma unroll
        for (int nf = 0; nf < 8; nf++) {
            sA += acc[mt][nf][0] + acc[mt][nf][1];
            s2A = fmaf(acc[mt][nf][0], acc[mt][nf][0], fmaf(acc[mt][nf][1], acc[mt][nf][1], s2A));
            sBv += acc[mt][nf][2] + acc[mt][nf][3];
            s2B = fmaf(acc[mt][nf][2], acc[mt][nf][2], fmaf(acc[mt][nf][3], acc[mt][nf][3], s2B));
        }
        sA = quad2(sA); s2A = quad2(s2A); sBv = quad2(sBv); s2B = quad2(s2B);
        if ((lane & 3) == 0) {
            const int R = wm * 32 + mt * 16 + (lane >> 2);
            psum[R][wn] = sA;       psum2[R][wn] = s2A;
            psum[R + 8][wn] = sBv;  psum2[R + 8][wn] = s2B;
        }
    }
    __syncthreads();

    float mu_[2][2], rs_[2][2];
#pragma unroll
    for (int mt = 0; mt < 2; mt++)
#pragma unroll
        for (int hf = 0; hf < 2; hf++) {
            const int R = wm * 32 + mt * 16 + (lane >> 2) + 8 * hf;
            const float S  = psum[R][0] + psum[R][1];
            const float S2 = psum2[R][0] + psum2[R][1];
            const float mu = S * (1.f / 128.f);
            mu_[mt][hf] = mu;
            rs_[mt][hf] = rsqrtf(S2 * (1.f / 128.f) - mu * mu + GNEPS);
        }

    if (MODE == 0) {
#pragma unroll
        for (int mt = 0; mt < 2; mt++) {
            float dpA = 0.f, k2A = 0.f, dpB = 0.f, k2B = 0.f;
#pragma unroll
            for (int nf = 0; nf < 8; nf++) {
                const int c = wn * 64 + nf * 8 + 2 * (lane & 3);
                float v0 = (acc[mt][nf][0] - mu_[mt][0]) * rs_[mt][0] * sg[c]     + sbeta[c];
                float v1 = (acc[mt][nf][1] - mu_[mt][0]) * rs_[mt][0] * sg[c + 1] + sbeta[c + 1];
                float v2 = (acc[mt][nf][2] - mu_[mt][1]) * rs_[mt][1] * sg[c]     + sbeta[c];
                float v3 = (acc[mt][nf][3] - mu_[mt][1]) * rs_[mt][1] * sg[c + 1] + sbeta[c + 1];
                dpA = fmaf(v0, sq[c], fmaf(v1, sq[c + 1], dpA));
                k2A = fmaf(v0, v0, fmaf(v1, v1, k2A));
                dpB = fmaf(v2, sq[c], fmaf(v3, sq[c + 1], dpB));
                k2B = fmaf(v2, v2, fmaf(v3, v3, k2B));
            }
            dpA = quad2(dpA); k2A = quad2(k2A); dpB = quad2(dpB); k2B = quad2(k2B);
            if ((lane & 3) == 0) {
                const int R = wm * 32 + mt * 16 + (lane >> 2);
                pdot[R][wn] = dpA;      pk2[R][wn] = k2A;
                pdot[R + 8][wn] = dpB;  pk2[R + 8][wn] = k2B;
            }
        }
        __syncthreads();
        if (wn == 0 && (lane & 3) == 0) {
#pragma unroll
            for (int mt = 0; mt < 2; mt++)
#pragma unroll
                for (int hf = 0; hf < 2; hf++) {
                    const int R = wm * 32 + mt * 16 + (lane >> 2) + 8 * hf;
                    const int m = (tm * 128 + R) & 1023;
                    g_dotb[bh2 * 1024 + m] = pdot[R][0] + pdot[R][1];
                    g_knb[bh2 * 1024 + m]  = sqrtf(pk2[R][0] + pk2[R][1]);
                }
        }
    } else {
#pragma unroll
        for (int mt = 0; mt < 2; mt++)
#pragma unroll
            for (int hf = 0; hf < 2; hf++) {
                const int R = wm * 32 + mt * 16 + (lane >> 2) + 8 * hf;
                const int m = (tm * 128 + R) & 1023;
                float* dst = g_v2s + ((size_t)bh2 * 1024 + m) * 128;
                const float mu = mu_[mt][hf], rstd = rs_[mt][hf];
#pragma unroll
                for (int nf = 0; nf < 8; nf++) {
                    const int c = wn * 64 + nf * 8 + 2 * (lane & 3);
                    const float v0 = (acc[mt][nf][2 * hf]     - mu) * rstd * sg[c]     + sbeta[c];
                    const float v1 = (acc[mt][nf][2 * hf + 1] - mu) * rstd * sg[c + 1] + sbeta[c + 1];
                    *(float2*)(dst + c) = make_float2(v0, v1);
                }
            }
    }
}

// ---------------- attention / pooling / output (proven) ----------------------
__device__ __forceinline__ float blockSum128(float v) {
    __shared__ float sh[4];
#pragma unroll
    for (int o = 16; o; o >>= 1) v += __shfl_xor_sync(0xffffffffu, v, o);
    if ((threadIdx.x & 31) == 0) sh[threadIdx.x >> 5] = v;
    __syncthreads();
    v = sh[0] + sh[1] + sh[2] + sh[3];
    __syncthreads();
    return v;
}
__device__ __forceinline__ float blockMax128(float v) {
    __shared__ float sh[4];
#pragma unroll
    for (int o = 16; o; o >>= 1) v = fmaxf(v, __shfl_xor_sync(0xffffffffu, v, o));
    if ((threadIdx.x & 31) == 0) sh[threadIdx.x >> 5] = v;
    __syncthreads();
    v = fmaxf(fmaxf(sh[0], sh[1]), fmaxf(sh[2], sh[3]));
    __syncthreads();
    return v;
}

__global__ __launch_bounds__(128) void attn_kernel(
    const float* __restrict__ mask,
    const float* __restrict__ W1,  const float* __restrict__ b1,
    const float* __restrict__ Wl,  const float* __restrict__ bl,
    const float* __restrict__ Wl2, const float* __restrict__ bl2,
    float* __restrict__ out)
{
    __shared__ float qdir[128], u[64], b1s[64], wls[64], pool[64];
    __shared__ float cosv[1024], aspv[1024], maskv[1024];

    const int bh  = blockIdx.x;
    const int b   = bh >> 3;
    const int tid = threadIdx.x;

    const float qv = g_qbuf[bh * 128 + tid];
    const float qn = sqrtf(blockSum128(qv * qv));
    qdir[tid] = qv / fmaxf(qn, 1e-12f);
    if (tid < 64) { b1s[tid] = b1[tid]; wls[tid] = Wl[tid]; }
    __syncthreads();

    if (tid < 64) {
        float a = 0.f;
#pragma unroll 4
        for (int d = 0; d < 128; d++) a = fmaf(qdir[d], W1[d * 64 + tid], a);
        u[tid] = a;
    }
    __syncthreads();

    const float qnc = fmaxf(qn, 1e-8f);
    const float bl0 = bl[0];

    float lmax = -1e30f, msum = 0.f;
#pragma unroll
    for (int mi = 0; mi < 8; mi++) {
        const int m = tid + mi * 128;
        const float kn = g_knb[bh * 1024 + m];
        const float cs = g_dotb[bh * 1024 + m] / (qnc * fmaxf(kn, 1e-8f));
        cosv[m] = cs;
        const float mk = mask[b * 1024 + m];
        maskv[m] = mk;
        msum += mk;
        float lg = bl0;
#pragma unroll 8
        for (int j = 0; j < 64; j++)
            lg = fmaf(fmaxf(fmaf(cs, u[j], b1s[j]), 0.f), wls[j], lg);
        if (mk == 0.f) lg = -1e9f;
        aspv[m] = lg;
        lmax = fmaxf(lmax, lg);
    }
    lmax = blockMax128(lmax);
    msum = blockSum128(msum);

    float esum = 0.f;
#pragma unroll
    for (int mi = 0; mi < 8; mi++) {
        const int m = tid + mi * 128;
        const float e = expf(aspv[m] - lmax);
        aspv[m] = e;
        esum += e;
    }
    esum = blockSum128(esum);
    const float inv = 1.f / esum;
    __syncthreads();

    if (tid < 64) {
        const float uj = u[tid], bj = b1s[tid];
        float p = 0.f;
#pragma unroll 8
        for (int m = 0; m < 1024; m++)
            p = fmaf(fmaxf(fmaf(cosv[m], uj, bj), 0.f), maskv[m], p);
        pool[tid] = p / msum;
    }
    __syncthreads();

    float a2 = bl2[tid];
#pragma unroll 8
    for (int j = 0; j < 64; j++) a2 = fmaf(pool[j], Wl2[j * 128 + tid], a2);
    const float ach = 1.f / (1.f + expf(-a2));

    const float* vb = g_v2s + (size_t)bh * 1024 * 128 + tid;
    float acc = 0.f;
#pragma unroll 8
    for (int m = 0; m < 1024; m++) acc = fmaf(aspv[m], vb[(size_t)m * 128], acc);
    acc *= inv;

    out[bh * 128 + tid] = g_v1buf[bh * 128 + tid] * acc * ach;
}

// ---------------- launch ------------------------------------------------------
extern "C" void kernel_launch(void* const* d_in, const int* in_sizes, int n_in,
                              void* d_out, int out_size) {
    const float* query   = (const float*)d_in[0];
    const float* key     = (const float*)d_in[1];
    const float* mask    = (const float*)d_in[2];
    const float* value1  = (const float*)d_in[3];
    const float* value2  = (const float*)d_in[4];
    const float* W_q     = (const float*)d_in[5];
    const float* b_q     = (const float*)d_in[6];
    const float* g_q     = (const float*)d_in[7];
    const float* beta_q  = (const float*)d_in[8];
    const float* W_k     = (const float*)d_in[9];
    const float* b_k     = (const float*)d_in[10];
    const float* g_k     = (const float*)d_in[11];
    const float* beta_k  = (const float*)d_in[12];
    const float* W_v1    = (const float*)d_in[13];
    const float* b_v1    = (const float*)d_in[14];
    const float* g_v1    = (const float*)d_in[15];
    const float* beta_v1 = (const float*)d_in[16];
    const float* W_v2    = (const float*)d_in[17];
    const float* b_v2    = (const float*)d_in[18];
    const float* g_v2    = (const float*)d_in[19];
    const float* beta_v2 = (const float*)d_in[20];
    const float* W1      = (const float*)d_in[21];
    const float* b1      = (const float*)d_in[22];
    const float* Wl      = (const float*)d_in[23];
    const float* bl      = (const float*)d_in[24];
    const float* Wl2     = (const float*)d_in[25];
    const float* bl2     = (const float*)d_in[26];
    float* out = (float*)d_out;

    convB_kernel<<<dim3(64, 8), 256>>>(W_k,  0);
    convB_kernel<<<dim3(64, 8), 256>>>(W_v2, 1);

    small_proj_kernel<0><<<512, 128>>>(query,  W_q,  b_q,  g_q,  beta_q);
    small_proj_kernel<1><<<512, 128>>>(value1, W_v1, b_v1, g_v1, beta_v1);

    big_mma_kernel<0><<<dim3(8, 512), 256>>>(key,    b_k,  g_k,  beta_k);
    big_mma_kernel<1><<<dim3(8, 512), 256>>>(value2, b_v2, g_v2, beta_v2);

    attn_kernel<<<512, 128>>>(mask, W1, b1, Wl, bl, Wl2, bl2, out);
}

// round 7
// speedup vs baseline: 2.3732x; 1.0434x over previous
#include <cuda_runtime.h>
#include <cuda_bf16.h>
#include <math.h>
#include <stdint.h>

#define ALPHA 1.3f
#define GNEPS 1e-5f
// B=64, M=1024, D=1024, H=8, HD=128

// ---------------- scratch (__device__ globals) -------------------------------
__device__ float g_qbuf[64 * 1024];
__device__ float g_v1buf[64 * 1024];
__device__ float g_dotb[64 * 8 * 1024];
__device__ float g_knb[64 * 8 * 1024];
__device__ float g_v2s[67108864];              // ((b*8+h)*1024+m)*128+c

// Pre-converted W^T tiles: [mode][ (h*64+kc)*128 + n ]*24 + k  (k16 chunks, pad 24)
__device__ __nv_bfloat16 g_Bhi[2][1572864];
__device__ __nv_bfloat16 g_Blo[2][1572864];

__device__ __forceinline__ float celu_f(float x) {
    return x > 0.f ? x : ALPHA * expm1f(x * (1.0f / ALPHA));
}

// ---------------- PTX helpers ------------------------------------------------
__device__ __forceinline__ uint32_t smem_u32(const void* p) {
    return (uint32_t)__cvta_generic_to_shared(p);
}
__device__ __forceinline__ void cp16(uint32_t dst, const void* src) {
    asm volatile("cp.async.cg.shared.global [%0], [%1], 16;\n"
                 :: "r"(dst), "l"(__cvta_generic_to_global(src)));
}
#define CP_COMMIT()  asm volatile("cp.async.commit_group;\n" ::: "memory")
#define CP_WAIT1()   asm volatile("cp.async.wait_group 1;\n" ::: "memory")
#define CP_WAIT0()   asm volatile("cp.async.wait_group 0;\n" ::: "memory")

__device__ __forceinline__ void ldsm4(uint32_t* d, uint32_t addr) {
    asm volatile("ldmatrix.sync.aligned.m8n8.x4.shared.b16 {%0,%1,%2,%3}, [%4];"
                 : "=r"(d[0]), "=r"(d[1]), "=r"(d[2]), "=r"(d[3]) : "r"(addr));
}
__device__ __forceinline__ void mma16816(float* c, const uint32_t* a,
                                         uint32_t b0, uint32_t b1) {
    asm volatile(
        "mma.sync.aligned.m16n8k16.row.col.f32.bf16.bf16.f32 "
        "{%0,%1,%2,%3}, {%4,%5,%6,%7}, {%8,%9}, {%0,%1,%2,%3};"
        : "+f"(c[0]), "+f"(c[1]), "+f"(c[2]), "+f"(c[3])
        : "r"(a[0]), "r"(a[1]), "r"(a[2]), "r"(a[3]), "r"(b0), "r"(b1));
}
__device__ __forceinline__ float quad2(float v) {
    v += __shfl_xor_sync(0xffffffffu, v, 1);
    v += __shfl_xor_sync(0xffffffffu, v, 2);
    return v;
}
__device__ __forceinline__ uint4 pack_hi8(const float* v, float* rem) {
    __nv_bfloat16 h[8];
#pragma unroll
    for (int i = 0; i < 8; i++) {
        h[i] = __float2bfloat16(v[i]);
        rem[i] = v[i] - __bfloat162float(h[i]);
    }
    uint4 r;
    __nv_bfloat162 p;
    p.x = h[0]; p.y = h[1]; r.x = *(uint32_t*)&p;
    p.x = h[2]; p.y = h[3]; r.y = *(uint32_t*)&p;
    p.x = h[4]; p.y = h[5]; r.z = *(uint32_t*)&p;
    p.x = h[6]; p.y = h[7]; r.w = *(uint32_t*)&p;
    return r;
}
__device__ __forceinline__ uint4 pack8(const float* v) {
    uint4 r;
    __nv_bfloat162 p;
    p.x = __float2bfloat16(v[0]); p.y = __float2bfloat16(v[1]); r.x = *(uint32_t*)&p;
    p.x = __float2bfloat16(v[2]); p.y = __float2bfloat16(v[3]); r.y = *(uint32_t*)&p;
    p.x = __float2bfloat16(v[4]); p.y = __float2bfloat16(v[5]); r.z = *(uint32_t*)&p;
    p.x = __float2bfloat16(v[6]); p.y = __float2bfloat16(v[7]); r.w = *(uint32_t*)&p;
    return r;
}

// ---------------- convB: W -> per-head [n][k] bf16 hi/lo padded tiles --------
__global__ __launch_bounds__(256) void convB_kernel(const float* __restrict__ W, int mode)
{
    const int kc = blockIdx.x, h = blockIdx.y, tid = threadIdx.x;
    const int n = tid & 127;
    const int kh = (tid >> 7) * 8;
    float vals[8], rem[8];
#pragma unroll
    for (int j = 0; j < 8; j++)
        vals[j] = W[(size_t)(kc * 16 + kh + j) * 1024 + h * 128 + n];
    const size_t base = ((size_t)(h * 64 + kc) * 128 + n) * 24 + kh;
    const uint4 hi = pack_hi8(vals, rem);
    const uint4 lo = pack8(rem);
    *(uint4*)&g_Bhi[mode][base] = hi;
    *(uint4*)&g_Blo[mode][base] = lo;
}

// ---------------- small projections: q, v1 (512 thr, 4-way K split) ----------
template <int DST>
__global__ __launch_bounds__(512) void small_proj_kernel(
    const float* __restrict__ X, const float* __restrict__ W,
    const float* __restrict__ bias, const float* __restrict__ gw,
    const float* __restrict__ betaw)
{
    __shared__ float xs[1024];
    __shared__ float part[4][128];
    __shared__ float sh[16];
    const int row = blockIdx.x >> 3;
    const int h   = blockIdx.x & 7;
    const int tid = threadIdx.x;
    const int c   = tid & 127;
    const int kq  = tid >> 7;           // 0..3

    if (tid < 256)
        ((float4*)xs)[tid] = ((const float4*)(X + (size_t)row * 1024))[tid];
    __syncthreads();

    const int col = h * 128 + c;
    const float* Wp = W + (size_t)(kq * 256) * 1024 + col;
    const float* xp = xs + kq * 256;
    float a = 0.f;
#pragma unroll 16
    for (int k = 0; k < 256; k++) a = fmaf(xp[k], Wp[(size_t)k * 1024], a);
    part[kq][c] = a;
    __syncthreads();

    float acc = 0.f;
    if (tid < 128)
        acc = celu_f(part[0][c] + part[1][c] + part[2][c] + part[3][c] + bias[col]);

    // block-wide sums over the 128 active values (others contribute 0)
    float s = acc, s2 = acc * acc;
#pragma unroll
    for (int o = 16; o; o >>= 1) {
        s  += __shfl_xor_sync(0xffffffffu, s,  o);
        s2 += __shfl_xor_sync(0xffffffffu, s2, o);
    }
    if ((tid & 31) == 0) { sh[tid >> 5] = s; sh[(tid >> 5) + 8] = s2; }
    __syncthreads();
    if (tid < 128) {
        s  = sh[0] + sh[1] + sh[2]  + sh[3];   // only warps 0-3 hold nonzero
        s2 = sh[8] + sh[9] + sh[10] + sh[11];
        const float mu   = s * (1.f / 128.f);
        const float rstd = rsqrtf(s2 * (1.f / 128.f) - mu * mu + GNEPS);
        const float v = (acc - mu) * rstd * gw[col] + betaw[col];
        if (DST == 0) g_qbuf[row * 1024 + col] = v;
        else          g_v1buf[row * 1024 + col] = v;
    }
}

// ---------------- merged tensor-core big projection GEMM ---------------------
// grid (8 heads, 512 row-tiles, 2 modes), 256 thr = 8 warps (4M x 2N).
// mode 0: key -> dot/kn ; mode 1: value2 -> g_v2s. Same proven mainloop.
__global__ __launch_bounds__(256, 2) void big_mma_kernel(
    const float* __restrict__ key,  const float* __restrict__ value2,
    const float* __restrict__ b_k,  const float* __restrict__ g_k,  const float* __restrict__ beta_k,
    const float* __restrict__ b_v,  const float* __restrict__ g_v,  const float* __restrict__ beta_v)
{
    __shared__ __align__(16) __nv_bfloat16 sAhi[128][24];
    __shared__ __align__(16) __nv_bfloat16 sAlo[128][24];
    __shared__ __align__(16) __nv_bfloat16 sB[2][2][128][24];
    __shared__ float sbias[128], sg[128], sbeta[128], sq[128];
    __shared__ float psum[128][2], psum2[128][2];
    __shared__ float pdot[128][2], pk2[128][2];

    const int h    = blockIdx.x;
    const int tm   = blockIdx.y;
    const int mode = blockIdx.z;
    const int tid  = threadIdx.x;
    const int lane = tid & 31;
    const int warp = tid >> 5;
    const int wm   = warp >> 1;
    const int wn   = warp & 1;
    const int col0 = h * 128;
    const int b0   = tm >> 3;

    const float* A     = mode ? value2 : key;
    const float* bias  = mode ? b_v    : b_k;
    const float* gw    = mode ? g_v    : g_k;
    const float* betaw = mode ? beta_v : beta_k;

    if (tid < 128) {
        sbias[tid] = bias[col0 + tid];
        sg[tid]    = gw[col0 + tid];
        sbeta[tid] = betaw[col0 + tid];
        sq[tid]    = (mode == 0) ? g_qbuf[b0 * 1024 + col0 + tid] : 0.f;
    }

    const int ar = tid >> 1;
    const int ak = (tid & 1) * 8;
    const float* Abase = A + (size_t)(tm * 128 + ar) * 1024 + ak;

    float pf[8];
    auto ldgA = [&](int kc) {
        const float4* p = (const float4*)(Abase + kc * 16);
        *(float4*)&pf[0] = p[0];
        *(float4*)&pf[4] = p[1];
    };
    const uint32_t aHiRow = smem_u32(&sAhi[ar][ak]);
    const uint32_t aLoRow = smem_u32(&sAlo[ar][ak]);
    auto storeA = [&]() {
        float rem[8];
        const uint4 hi = pack_hi8(pf, rem);
        const uint4 lo = pack8(rem);
        *(uint4*)__cvta_shared_to_generic(aHiRow) = hi;
        *(uint4*)__cvta_shared_to_generic(aLoRow) = lo;
    };

    const __nv_bfloat16* Bhi = g_Bhi[mode];
    const __nv_bfloat16* Blo = g_Blo[mode];
    const uint32_t sB0 = smem_u32(&sB[0][0][0][0]);
    auto cpB = [&](int kc, int stg) {
        const size_t tb = (size_t)(h * 64 + kc) * 3072;
        const uint32_t d = sB0 + (uint32_t)stg * 12288u;
        cp16(d + (uint32_t)tid * 16u, Bhi + tb + (size_t)tid * 8);
        if (tid < 128) cp16(d + (uint32_t)(tid + 256) * 16u, Bhi + tb + (size_t)(tid + 256) * 8);
        cp16(d + 6144u + (uint32_t)tid * 16u, Blo + tb + (size_t)tid * 8);
        if (tid < 128) cp16(d + 6144u + (uint32_t)(tid + 256) * 16u, Blo + tb + (size_t)(tid + 256) * 8);
    };

    const uint32_t aHi = smem_u32(sAhi), aLo = smem_u32(sAlo);
    const uint32_t klane = (uint32_t)(((lane >> 4) & 1) * 16);
    uint32_t aoff[2];
#pragma unroll
    for (int mt = 0; mt < 2; mt++) {
        const int r = wm * 32 + mt * 16 + (lane & 7) + 8 * ((lane >> 3) & 1);
        aoff[mt] = (uint32_t)r * 48u + klane;
    }
    uint32_t boff[4];
#pragma unroll
    for (int bp = 0; bp < 4; bp++) {
        const int n = wn * 64 + bp * 16 + (lane & 7) + 8 * ((lane >> 3) & 1);
        boff[bp] = (uint32_t)n * 48u + klane;
    }

    float acc[2][8][4];
#pragma unroll
    for (int mt = 0; mt < 2; mt++)
#pragma unroll
        for (int nf = 0; nf < 8; nf++)
#pragma unroll
            for (int q = 0; q < 4; q++) acc[mt][nf][q] = 0.f;

    ldgA(0);
    cpB(0, 0);
    CP_COMMIT();

    for (int kc = 0; kc < 64; kc++) {
        storeA();
        if (kc < 63) { cpB(kc + 1, (kc + 1) & 1); CP_COMMIT(); CP_WAIT1(); }
        else         { CP_WAIT0(); }
        __syncthreads();
        if (kc < 63) ldgA(kc + 1);

        const uint32_t bbase = sB0 + (uint32_t)(kc & 1) * 12288u;
        uint32_t ah[2][4], al[2][4];
#pragma unroll
        for (int mt = 0; mt < 2; mt++) {
            ldsm4(ah[mt], aHi + aoff[mt]);
            ldsm4(al[mt], aLo + aoff[mt]);
        }
#pragma unroll
        for (int bp = 0; bp < 4; bp++) {
            uint32_t bh[4], bl[4];
            ldsm4(bh, bbase + boff[bp]);
            ldsm4(bl, bbase + 6144u + boff[bp]);
#pragma unroll
            for (int mt = 0; mt < 2; mt++) {
                mma16816(acc[mt][2 * bp],     ah[mt], bh[0], bh[2]);
                mma16816(acc[mt][2 * bp + 1], ah[mt], bh[1], bh[3]);
                mma16816(acc[mt][2 * bp],     ah[mt], bl[0], bl[2]);
                mma16816(acc[mt][2 * bp + 1], ah[mt], bl[1], bl[3]);
                mma16816(acc[mt][2 * bp],     al[mt], bh[0], bh[2]);
                mma16816(acc[mt][2 * bp + 1], al[mt], bh[1], bh[3]);
            }
        }
        __syncthreads();
    }

    // ---- register epilogue (proven) ----
    const int bh2 = b0 * 8 + h;
#pragma unroll
    for (int mt = 0; mt < 2; mt++)
#pragma unroll
        for (int nf = 0; nf < 8; nf++) {
            const int c = wn * 64 + nf * 8 + 2 * (lane & 3);
            acc[mt][nf][0] = celu_f(acc[mt][nf][0] + sbias[c]);
            acc[mt][nf][1] = celu_f(acc[mt][nf][1] + sbias[c + 1]);
            acc[mt][nf][2] = celu_f(acc[mt][nf][2] + sbias[c]);
            acc[mt][nf][3] = celu_f(acc[mt][nf][3] + sbias[c + 1]);
        }

#pragma unroll
    for (int mt = 0; mt < 2; mt++) {
        float sA = 0.f, s2A = 0.f, sBv = 0.f, s2B = 0.f;
#pragma unroll
        for (int nf = 0; nf < 8; nf++) {
            sA += acc[mt][nf][0] + acc[mt][nf][1];
            s2A = fmaf(acc[mt][nf][0], acc[mt][nf][0], fmaf(acc[mt][nf][1], acc[mt][nf][1], s2A));
            sBv += acc[mt][nf][2] + acc[mt][nf][3];
            s2B = fmaf(acc[mt][nf][2], acc[mt][nf][2], fmaf(acc[mt][nf][3], acc[mt][nf][3], s2B));
        }
        sA = quad2(sA); s2A = quad2(s2A); sBv = quad2(sBv); s2B = quad2(s2B);
        if ((lane & 3) == 0) {
            const int R = wm * 32 + mt * 16 + (lane >> 2);
            psum[R][wn] = sA;       psum2[R][wn] = s2A;
            psum[R + 8][wn] = sBv;  psum2[R + 8][wn] = s2B;
        }
    }
    __syncthreads();

    float mu_[2][2], rs_[2][2];
#pragma unroll
    for (int mt = 0; mt < 2; mt++)
#pragma unroll
        for (int hf = 0; hf < 2; hf++) {
            const int R = wm * 32 + mt * 16 + (lane >> 2) + 8 * hf;
            const float S  = psum[R][0] + psum[R][1];
            const float S2 = psum2[R][0] + psum2[R][1];
            const float mu = S * (1.f / 128.f);
            mu_[mt][hf] = mu;
            rs_[mt][hf] = rsqrtf(S2 * (1.f / 128.f) - mu * mu + GNEPS);
        }

    if (mode == 0) {
#pragma unroll
        for (int mt = 0; mt < 2; mt++) {
            float dpA = 0.f, k2A = 0.f, dpB = 0.f, k2B = 0.f;
#pragma unroll
            for (int nf = 0; nf < 8; nf++) {
                const int c = wn * 64 + nf * 8 + 2 * (lane & 3);
                float v0 = (acc[mt][nf][0] - mu_[mt][0]) * rs_[mt][0] * sg[c]     + sbeta[c];
                float v1 = (acc[mt][nf][1] - mu_[mt][0]) * rs_[mt][0] * sg[c + 1] + sbeta[c + 1];
                float v2 = (acc[mt][nf][2] - mu_[mt][1]) * rs_[mt][1] * sg[c]     + sbeta[c];
                float v3 = (acc[mt][nf][3] - mu_[mt][1]) * rs_[mt][1] * sg[c + 1] + sbeta[c + 1];
                dpA = fmaf(v0, sq[c], fmaf(v1, sq[c + 1], dpA));
                k2A = fmaf(v0, v0, fmaf(v1, v1, k2A));
                dpB = fmaf(v2, sq[c], fmaf(v3, sq[c + 1], dpB));
                k2B = fmaf(v2, v2, fmaf(v3, v3, k2B));
            }
            dpA = quad2(dpA); k2A = quad2(k2A); dpB = quad2(dpB); k2B = quad2(k2B);
            if ((lane & 3) == 0) {
                const int R = wm * 32 + mt * 16 + (lane >> 2);
                pdot[R][wn] = dpA;      pk2[R][wn] = k2A;
                pdot[R + 8][wn] = dpB;  pk2[R + 8][wn] = k2B;
            }
        }
        __syncthreads();
        if (wn == 0 && (lane & 3) == 0) {
#pragma unroll
            for (int mt = 0; mt < 2; mt++)
#pragma unroll
                for (int hf = 0; hf < 2; hf++) {
                    const int R = wm * 32 + mt * 16 + (lane >> 2) + 8 * hf;
                    const int m = (tm * 128 + R) & 1023;
                    g_dotb[bh2 * 1024 + m] = pdot[R][0] + pdot[R][1];
                    g_knb[bh2 * 1024 + m]  = sqrtf(pk2[R][0] + pk2[R][1]);
                }
        }
    } else {
#pragma unroll
        for (int mt = 0; mt < 2; mt++)
#pragma unroll
            for (int hf = 0; hf < 2; hf++) {
                const int R = wm * 32 + mt * 16 + (lane >> 2) + 8 * hf;
                const int m = (tm * 128 + R) & 1023;
                float* dst = g_v2s + ((size_t)bh2 * 1024 + m) * 128;
                const float mu = mu_[mt][hf], rstd = rs_[mt][hf];
#pragma unroll
                for (int nf = 0; nf < 8; nf++) {
                    const int c = wn * 64 + nf * 8 + 2 * (lane & 3);
                    const float v0 = (acc[mt][nf][2 * hf]     - mu) * rstd * sg[c]     + sbeta[c];
                    const float v1 = (acc[mt][nf][2 * hf + 1] - mu) * rstd * sg[c + 1] + sbeta[c + 1];
                    *(float2*)(dst + c) = make_float2(v0, v1);
                }
            }
    }
}

// ---------------- attention / pooling / output (256 threads) -----------------
__device__ __forceinline__ float bsum256(float v, float* sh) {
#pragma unroll
    for (int o = 16; o; o >>= 1) v += __shfl_xor_sync(0xffffffffu, v, o);
    if ((threadIdx.x & 31) == 0) sh[threadIdx.x >> 5] = v;
    __syncthreads();
    v = (sh[0] + sh[1]) + (sh[2] + sh[3]) + ((sh[4] + sh[5]) + (sh[6] + sh[7]));
    __syncthreads();
    return v;
}
__device__ __forceinline__ float bmax256(float v, float* sh) {
#pragma unroll
    for (int o = 16; o; o >>= 1) v = fmaxf(v, __shfl_xor_sync(0xffffffffu, v, o));
    if ((threadIdx.x & 31) == 0) sh[threadIdx.x >> 5] = v;
    __syncthreads();
    v = fmaxf(fmaxf(fmaxf(sh[0], sh[1]), fmaxf(sh[2], sh[3])),
              fmaxf(fmaxf(sh[4], sh[5]), fmaxf(sh[6], sh[7])));
    __syncthreads();
    return v;
}

__global__ __launch_bounds__(256) void attn_kernel(
    const float* __restrict__ mask,
    const float* __restrict__ W1,  const float* __restrict__ b1,
    const float* __restrict__ Wl,  const float* __restrict__ bl,
    const float* __restrict__ Wl2, const float* __restrict__ bl2,
    float* __restrict__ out)
{
    __shared__ float qdir[128], u[64], b1s[64], wls[64], pool[64];
    __shared__ float cosv[1024], aspv[1024], maskv[1024];
    __shared__ float pp[4][64], vo[2][128];
    __shared__ float sh[8];

    const int bh  = blockIdx.x;
    const int b   = bh >> 3;
    const int tid = threadIdx.x;

    // q norm + direction (upper threads contribute 0)
    const float qv = (tid < 128) ? g_qbuf[bh * 128 + tid] : 0.f;
    const float qn = sqrtf(bsum256(qv * qv, sh));
    if (tid < 128) qdir[tid] = qv / fmaxf(qn, 1e-12f);
    if (tid < 64) { b1s[tid] = b1[tid]; wls[tid] = Wl[tid]; }
    __syncthreads();

    if (tid < 64) {
        float a = 0.f;
#pragma unroll 4
        for (int d = 0; d < 128; d++) a = fmaf(qdir[d], W1[d * 64 + tid], a);
        u[tid] = a;
    }
    __syncthreads();

    const float qnc = fmaxf(qn, 1e-8f);
    const float bl0 = bl[0];

    // phase 1: cos, spatial logits, mask (4 m per thread)
    float lmax = -1e30f, msum = 0.f;
#pragma unroll
    for (int mi = 0; mi < 4; mi++) {
        const int m = tid + mi * 256;
        const float kn = g_knb[bh * 1024 + m];
        const float cs = g_dotb[bh * 1024 + m] / (qnc * fmaxf(kn, 1e-8f));
        cosv[m] = cs;
        const float mk = mask[b * 1024 + m];
        maskv[m] = mk;
        msum += mk;
        float lg = bl0;
#pragma unroll 8
        for (int j = 0; j < 64; j++)
            lg = fmaf(fmaxf(fmaf(cs, u[j], b1s[j]), 0.f), wls[j], lg);
        if (mk == 0.f) lg = -1e9f;
        aspv[m] = lg;
        lmax = fmaxf(lmax, lg);
    }
    lmax = bmax256(lmax, sh);
    msum = bsum256(msum, sh);

    float esum = 0.f;
#pragma unroll
    for (int mi = 0; mi < 4; mi++) {
        const int m = tid + mi * 256;
        const float e = expf(aspv[m] - lmax);
        aspv[m] = e;
        esum += e;
    }
    esum = bsum256(esum, sh);
    const float inv = 1.f / esum;
    __syncthreads();

    // pool: j = tid&63 over quarter tid>>6 (256 m each)
    {
        const int j = tid & 63, qtr = tid >> 6;
        const float uj = u[j], bj = b1s[j];
        float p = 0.f;
        const int m0 = qtr * 256;
#pragma unroll 8
        for (int m = m0; m < m0 + 256; m++)
            p = fmaf(fmaxf(fmaf(cosv[m], uj, bj), 0.f), maskv[m], p);
        pp[qtr][j] = p;
    }
    __syncthreads();
    if (tid < 64)
        pool[tid] = (pp[0][tid] + pp[1][tid] + pp[2][tid] + pp[3][tid]) / msum;
    __syncthreads();

    // v2o: c = tid&127 over half tid>>7 (512 m each)
    {
        const int c = tid & 127, hf = tid >> 7;
        const float* vb = g_v2s + (size_t)bh * 131072 + (size_t)(hf * 512) * 128 + c;
        const float* av = aspv + hf * 512;
        float a = 0.f;
#pragma unroll 8
        for (int m = 0; m < 512; m++) a = fmaf(av[m], vb[(size_t)m * 128], a);
        vo[hf][c] = a;
    }
    __syncthreads();

    if (tid < 128) {
        float a2 = bl2[tid];
#pragma unroll 8
        for (int j = 0; j < 64; j++) a2 = fmaf(pool[j], Wl2[j * 128 + tid], a2);
        const float ach = 1.f / (1.f + expf(-a2));
        const float v2o = (vo[0][tid] + vo[1][tid]) * inv;
        out[bh * 128 + tid] = g_v1buf[bh * 128 + tid] * v2o * ach;
    }
}

// ---------------- launch ------------------------------------------------------
extern "C" void kernel_launch(void* const* d_in, const int* in_sizes, int n_in,
                              void* d_out, int out_size) {
    const float* query   = (const float*)d_in[0];
    const float* key     = (const float*)d_in[1];
    const float* mask    = (const float*)d_in[2];
    const float* value1  = (const float*)d_in[3];
    const float* value2  = (const float*)d_in[4];
    const float* W_q     = (const float*)d_in[5];
    const float* b_q     = (const float*)d_in[6];
    const float* g_q     = (const float*)d_in[7];
    const float* beta_q  = (const float*)d_in[8];
    const float* W_k     = (const float*)d_in[9];
    const float* b_k     = (const float*)d_in[10];
    const float* g_k     = (const float*)d_in[11];
    const float* beta_k  = (const float*)d_in[12];
    const float* W_v1    = (const float*)d_in[13];
    const float* b_v1    = (const float*)d_in[14];
    const float* g_v1    = (const float*)d_in[15];
    const float* beta_v1 = (const float*)d_in[16];
    const float* W_v2    = (const float*)d_in[17];
    const float* b_v2    = (const float*)d_in[18];
    const float* g_v2    = (const float*)d_in[19];
    const float* beta_v2 = (const float*)d_in[20];
    const float* W1      = (const float*)d_in[21];
    const float* b1      = (const float*)d_in[22];
    const float* Wl      = (const float*)d_in[23];
    const float* bl      = (const float*)d_in[24];
    const float* Wl2     = (const float*)d_in[25];
    const float* bl2     = (const float*)d_in[26];
    float* out = (float*)d_out;

    convB_kernel<<<dim3(64, 8), 256>>>(W_k,  0);
    convB_kernel<<<dim3(64, 8), 256>>>(W_v2, 1);

    small_proj_kernel<0><<<512, 512>>>(query,  W_q,  b_q,  g_q,  beta_q);
    small_proj_kernel<1><<<512, 512>>>(value1, W_v1, b_v1, g_v1, beta_v1);

    big_mma_kernel<<<dim3(8, 512, 2), 256>>>(key, value2,
                                             b_k,  g_k,  beta_k,
                                             b_v2, g_v2, beta_v2);

    attn_kernel<<<512, 256>>>(mask, W1, b1, Wl, bl, Wl2, bl2, out);
}